// round 1
// baseline (speedup 1.0000x reference)
#include <cuda_runtime.h>
#include <math.h>

// Problem constants
#define BB 2
#define LL 2048
#define DD 768
#define HH 12
#define HD 64
#define ND3 2304   // 3*D

// Scratch (device globals: allocation-free rule)
__device__ float g_Q[BB * HH * LL * HD];     // [b][h][l][d]
__device__ float g_K[BB * HH * LL * HD];
__device__ float g_V[BB * HH * LL * HD];
__device__ float g_attn[BB * LL * DD];       // [b][l][h*64+d]
__device__ float g_lsum[BB * HH * LL];       // softmax denominators

// ---------------------------------------------------------------------------
// Kernel 1: QKV projection. X[4096,768] @ W[768,2304] + bias,
// epilogue scatters into g_Q/g_K/g_V with head split [b][h][l][d].
// 128x128 tile, BK=8, 256 threads, 8x8 per thread.
// ---------------------------------------------------------------------------
__global__ __launch_bounds__(256) void qkv_gemm_kernel(
    const float* __restrict__ X, const float* __restrict__ W,
    const float* __restrict__ bias)
{
    __shared__ float As[8][128];
    __shared__ float Bs[8][128];
    const int tid = threadIdx.x;
    const int tx = tid & 15, ty = tid >> 4;
    const int row0 = blockIdx.y * 128;
    const int col0 = blockIdx.x * 128;

    float acc[8][8];
    #pragma unroll
    for (int i = 0; i < 8; i++)
        #pragma unroll
        for (int j = 0; j < 8; j++) acc[i][j] = 0.f;

    const int a_row = tid >> 1;         // 0..127
    const int a_col = (tid & 1) * 4;    // 0 or 4
    const int b_row = tid >> 5;         // 0..7
    const int b_col = (tid & 31) * 4;   // 0..124

    for (int k0 = 0; k0 < DD; k0 += 8) {
        float4 av = *(const float4*)(X + (size_t)(row0 + a_row) * DD + k0 + a_col);
        As[a_col + 0][a_row] = av.x;
        As[a_col + 1][a_row] = av.y;
        As[a_col + 2][a_row] = av.z;
        As[a_col + 3][a_row] = av.w;
        float4 bv = *(const float4*)(W + (size_t)(k0 + b_row) * ND3 + col0 + b_col);
        *(float4*)(&Bs[b_row][b_col]) = bv;
        __syncthreads();
        #pragma unroll
        for (int kk = 0; kk < 8; kk++) {
            float a[8], b[8];
            *(float4*)(a)     = *(const float4*)(&As[kk][ty * 8]);
            *(float4*)(a + 4) = *(const float4*)(&As[kk][ty * 8 + 4]);
            *(float4*)(b)     = *(const float4*)(&Bs[kk][tx * 8]);
            *(float4*)(b + 4) = *(const float4*)(&Bs[kk][tx * 8 + 4]);
            #pragma unroll
            for (int i = 0; i < 8; i++)
                #pragma unroll
                for (int j = 0; j < 8; j++) acc[i][j] += a[i] * b[j];
        }
        __syncthreads();
    }

    // Epilogue: route to Q/K/V per-head layout
    #pragma unroll
    for (int i = 0; i < 8; i++) {
        const int r = row0 + ty * 8 + i;
        const int bb = r >> 11;        // /2048
        const int l  = r & 2047;
        #pragma unroll
        for (int j = 0; j < 8; j++) {
            const int c = col0 + tx * 8 + j;
            float v = acc[i][j] + bias[c];
            const int which = c / DD;
            const int rem = c - which * DD;
            const int h = rem >> 6;
            const int d = rem & 63;
            const size_t dst = (((size_t)(bb * HH + h)) * LL + l) * HD + d;
            float* out = (which == 0) ? g_Q : (which == 1) ? g_K : g_V;
            out[dst] = v;
        }
    }
}

// ---------------------------------------------------------------------------
// Kernel 2: RoPE on Q and K in place. One thread per (b,h,l,t), t in [0,32).
// ---------------------------------------------------------------------------
__global__ __launch_bounds__(256) void rope_kernel()
{
    const int idx = blockIdx.x * blockDim.x + threadIdx.x;   // [0, B*H*L*32)
    const int t = idx & 31;
    const int l = (idx >> 5) & (LL - 1);
    const int bh = idx >> 16;  // / (32*2048)
    if (bh >= BB * HH) return;

    const float inv_freq = powf(10000.0f, -(float)t / 32.0f);
    const float angle = (float)l * inv_freq;
    const float c = cosf(angle);
    const float s = sinf(angle);

    const size_t base = ((size_t)bh * LL + l) * HD;
    {
        float x1 = g_Q[base + t], x2 = g_Q[base + t + 32];
        g_Q[base + t]      = x1 * c - x2 * s;
        g_Q[base + t + 32] = x2 * c + x1 * s;
    }
    {
        float x1 = g_K[base + t], x2 = g_K[base + t + 32];
        g_K[base + t]      = x1 * c - x2 * s;
        g_K[base + t + 32] = x2 * c + x1 * s;
    }
}

// ---------------------------------------------------------------------------
// Kernel 3: causal attention. Block = (qtile of 64, h, b). 256 threads.
// Streams 64-key tiles: S = Q K^T, p = exp(s/sqrt(L)) (no max-sub; scores
// are tiny), write unnormalized p to probs, accumulate O and row sums.
// Dynamic smem: Qs,Ks (d-major 64x64), Vs (k-major), Ps (q-major) = 64KB.
// ---------------------------------------------------------------------------
__global__ __launch_bounds__(256) void attn_kernel(float* __restrict__ probs)
{
    extern __shared__ float sm[];
    float* Qs = sm;          // Qs[d*64 + qi]
    float* Ks = sm + 4096;   // Ks[d*64 + kj]
    float* Vs = sm + 8192;   // Vs[k*64 + d]
    float* Ps = sm + 12288;  // Ps[qi*64 + kj]
    __shared__ float ls[64];

    const int tid = threadIdx.x;
    const int tx = tid & 15, ty = tid >> 4;
    const int q0 = blockIdx.x * 64;
    const int h = blockIdx.y, bb = blockIdx.z;
    const size_t bh = (size_t)bb * HH + h;

    const float* Qb = g_Q + (bh * LL + q0) * HD;
    const float* Kb = g_K + bh * LL * HD;
    const float* Vb = g_V + bh * LL * HD;
    float* Pb = probs + (bh * LL + q0) * LL;

    // Load Q tile transposed (d-major)
    #pragma unroll
    for (int t = 0; t < 4; t++) {
        int fi = tid + t * 256;             // float4 idx 0..1023
        int qi = fi >> 4;
        int d4 = (fi & 15) << 2;
        float4 v = *(const float4*)(Qb + qi * HD + d4);
        Qs[(d4 + 0) * 64 + qi] = v.x;
        Qs[(d4 + 1) * 64 + qi] = v.y;
        Qs[(d4 + 2) * 64 + qi] = v.z;
        Qs[(d4 + 3) * 64 + qi] = v.w;
    }
    if (tid < 64) ls[tid] = 0.f;

    float o[4][4];
    #pragma unroll
    for (int i = 0; i < 4; i++)
        #pragma unroll
        for (int j = 0; j < 4; j++) o[i][j] = 0.f;

    const float scale = rsqrtf(2048.0f);
    __syncthreads();

    const int ntiles = blockIdx.x + 1;  // key tiles with any unmasked entry
    for (int kt = 0; kt < 32; kt++) {
        const int k0 = kt * 64;
        if (kt >= ntiles) {
            // fully masked: write zeros (d_out is poisoned)
            float4 z = make_float4(0.f, 0.f, 0.f, 0.f);
            #pragma unroll
            for (int t = 0; t < 4; t++) {
                int fi = tid + t * 256;
                int qi = fi >> 4;
                int kg = (fi & 15) << 2;
                *(float4*)(Pb + (size_t)qi * LL + k0 + kg) = z;
            }
            continue;
        }

        // Load K (transposed) and V tiles
        #pragma unroll
        for (int t = 0; t < 4; t++) {
            int fi = tid + t * 256;
            int kj = fi >> 4;
            int d4 = (fi & 15) << 2;
            float4 v = *(const float4*)(Kb + (size_t)(k0 + kj) * HD + d4);
            Ks[(d4 + 0) * 64 + kj] = v.x;
            Ks[(d4 + 1) * 64 + kj] = v.y;
            Ks[(d4 + 2) * 64 + kj] = v.z;
            Ks[(d4 + 3) * 64 + kj] = v.w;
            float4 vv = *(const float4*)(Vb + (size_t)(k0 + kj) * HD + d4);
            *(float4*)(Vs + fi * 4) = vv;
        }
        __syncthreads();

        // S = Q K^T
        float s[4][4];
        #pragma unroll
        for (int i = 0; i < 4; i++)
            #pragma unroll
            for (int j = 0; j < 4; j++) s[i][j] = 0.f;
        #pragma unroll
        for (int d = 0; d < 64; d++) {
            float a[4], b[4];
            *(float4*)a = *(const float4*)(Qs + d * 64 + ty * 4);
            *(float4*)b = *(const float4*)(Ks + d * 64 + tx * 4);
            #pragma unroll
            for (int i = 0; i < 4; i++)
                #pragma unroll
                for (int j = 0; j < 4; j++) s[i][j] += a[i] * b[j];
        }

        // exp + causal mask -> Ps
        #pragma unroll
        for (int i = 0; i < 4; i++) {
            const int qg = q0 + ty * 4 + i;
            #pragma unroll
            for (int j = 0; j < 4; j++) {
                const int kg = k0 + tx * 4 + j;
                float p = (kg <= qg) ? __expf(s[i][j] * scale) : 0.f;
                Ps[(ty * 4 + i) * 64 + tx * 4 + j] = p;
            }
        }
        __syncthreads();

        // row sums
        if (tid < 64) {
            float acc = 0.f;
            #pragma unroll 16
            for (int k = 0; k < 64; k++) acc += Ps[tid * 64 + k];
            ls[tid] += acc;
        }

        // write unnormalized probs (coalesced float4)
        #pragma unroll
        for (int t = 0; t < 4; t++) {
            int fi = tid + t * 256;
            int qi = fi >> 4;
            int kg = (fi & 15) << 2;
            *(float4*)(Pb + (size_t)qi * LL + k0 + kg) =
                *(const float4*)(Ps + qi * 64 + kg);
        }

        // O += P V
        #pragma unroll
        for (int k = 0; k < 64; k++) {
            float b[4];
            *(float4*)b = *(const float4*)(Vs + k * 64 + tx * 4);
            float a[4];
            #pragma unroll
            for (int i = 0; i < 4; i++) a[i] = Ps[(ty * 4 + i) * 64 + k];
            #pragma unroll
            for (int i = 0; i < 4; i++)
                #pragma unroll
                for (int j = 0; j < 4; j++) o[i][j] += a[i] * b[j];
        }
        __syncthreads();
    }

    // Finalize: divide by row sums, write attn scratch [b][l][h*64+d]
    #pragma unroll
    for (int i = 0; i < 4; i++) {
        const int qi = ty * 4 + i;
        const float inv = 1.0f / ls[qi];
        float4 vv = make_float4(o[i][0] * inv, o[i][1] * inv,
                                o[i][2] * inv, o[i][3] * inv);
        *(float4*)(g_attn + ((size_t)bb * LL + q0 + qi) * DD + h * HD + tx * 4) = vv;
    }
    if (tid < 64) g_lsum[bh * LL + q0 + tid] = ls[tid];
}

// ---------------------------------------------------------------------------
// Kernel 4: normalize probs in place by row sums. float4 grid.
// Total f4 = B*H*L*L/4 = 25,165,824. 512 f4 per row.
// ---------------------------------------------------------------------------
__global__ __launch_bounds__(256) void norm_kernel(float* __restrict__ probs)
{
    const size_t i = (size_t)blockIdx.x * blockDim.x + threadIdx.x;  // f4 index
    const size_t row = i >> 9;  // / 512
    const float inv = 1.0f / g_lsum[row];
    float4 v = ((float4*)probs)[i];
    v.x *= inv; v.y *= inv; v.z *= inv; v.w *= inv;
    ((float4*)probs)[i] = v;
}

// ---------------------------------------------------------------------------
// Kernel 5: output projection. g_attn[4096,768] @ w_out[768,768] + b_out.
// Same SGEMM structure as kernel 1.
// ---------------------------------------------------------------------------
__global__ __launch_bounds__(256) void out_gemm_kernel(
    const float* __restrict__ W, const float* __restrict__ bias,
    float* __restrict__ out)
{
    __shared__ float As[8][128];
    __shared__ float Bs[8][128];
    const int tid = threadIdx.x;
    const int tx = tid & 15, ty = tid >> 4;
    const int row0 = blockIdx.y * 128;
    const int col0 = blockIdx.x * 128;

    float acc[8][8];
    #pragma unroll
    for (int i = 0; i < 8; i++)
        #pragma unroll
        for (int j = 0; j < 8; j++) acc[i][j] = 0.f;

    const int a_row = tid >> 1;
    const int a_col = (tid & 1) * 4;
    const int b_row = tid >> 5;
    const int b_col = (tid & 31) * 4;

    for (int k0 = 0; k0 < DD; k0 += 8) {
        float4 av = *(const float4*)(g_attn + (size_t)(row0 + a_row) * DD + k0 + a_col);
        As[a_col + 0][a_row] = av.x;
        As[a_col + 1][a_row] = av.y;
        As[a_col + 2][a_row] = av.z;
        As[a_col + 3][a_row] = av.w;
        float4 bv = *(const float4*)(W + (size_t)(k0 + b_row) * DD + col0 + b_col);
        *(float4*)(&Bs[b_row][b_col]) = bv;
        __syncthreads();
        #pragma unroll
        for (int kk = 0; kk < 8; kk++) {
            float a[8], b[8];
            *(float4*)(a)     = *(const float4*)(&As[kk][ty * 8]);
            *(float4*)(a + 4) = *(const float4*)(&As[kk][ty * 8 + 4]);
            *(float4*)(b)     = *(const float4*)(&Bs[kk][tx * 8]);
            *(float4*)(b + 4) = *(const float4*)(&Bs[kk][tx * 8 + 4]);
            #pragma unroll
            for (int i = 0; i < 8; i++)
                #pragma unroll
                for (int j = 0; j < 8; j++) acc[i][j] += a[i] * b[j];
        }
        __syncthreads();
    }

    #pragma unroll
    for (int i = 0; i < 8; i++) {
        const int r = row0 + ty * 8 + i;
        #pragma unroll
        for (int j = 0; j < 8; j += 4) {
            const int c = col0 + tx * 8 + j;
            float4 v = make_float4(acc[i][j + 0] + bias[c + 0],
                                   acc[i][j + 1] + bias[c + 1],
                                   acc[i][j + 2] + bias[c + 2],
                                   acc[i][j + 3] + bias[c + 3]);
            *(float4*)(out + (size_t)r * DD + c) = v;
        }
    }
}

// ---------------------------------------------------------------------------
extern "C" void kernel_launch(void* const* d_in, const int* in_sizes, int n_in,
                              void* d_out, int out_size)
{
    const float* X     = (const float*)d_in[0];  // [B,L,D]
    const float* w_qkv = (const float*)d_in[1];  // [D,3D]
    const float* b_qkv = (const float*)d_in[2];  // [3D]
    const float* w_out = (const float*)d_in[3];  // [D,D]
    const float* b_out = (const float*)d_in[4];  // [D]

    float* out   = (float*)d_out;                       // [B,L,D]
    float* probs = out + (size_t)BB * LL * DD;          // [B,H,L,L]

    // 1. QKV projection -> per-head Q/K/V
    qkv_gemm_kernel<<<dim3(ND3 / 128, (BB * LL) / 128), 256>>>(X, w_qkv, b_qkv);

    // 2. RoPE on Q,K
    rope_kernel<<<(BB * HH * LL * 32) / 256, 256>>>();

    // 3. Attention (dynamic smem 64KB)
    cudaFuncSetAttribute(attn_kernel,
                         cudaFuncAttributeMaxDynamicSharedMemorySize, 65536);
    attn_kernel<<<dim3(LL / 64, HH, BB), 256, 65536>>>(probs);

    // 4. Normalize probs
    norm_kernel<<<(int)(((size_t)BB * HH * LL * LL / 4) / 256), 256>>>(probs);

    // 5. Output projection
    out_gemm_kernel<<<dim3(DD / 128, (BB * LL) / 128), 256>>>(w_out, b_out, out);
}

// round 2
// speedup vs baseline: 1.0429x; 1.0429x over previous
#include <cuda_runtime.h>
#include <math.h>

// Problem constants
#define BB 2
#define LL 2048
#define DD 768
#define HH 12
#define HD 64
#define ND3 2304   // 3*D

// Scratch (device globals: allocation-free rule)
__device__ float g_Q[BB * HH * LL * HD];     // [b][h][l][d]
__device__ float g_K[BB * HH * LL * HD];
__device__ float g_V[BB * HH * LL * HD];
__device__ float g_attn[BB * LL * DD];       // [b][l][h*64+d]
__device__ float g_lsum[BB * HH * LL];       // softmax denominators

// ---------------------------------------------------------------------------
// Packed fp32x2 FMA helpers (FFMA2 — 2x fp32 throughput on the FMA pipe;
// only reachable via PTX fma.rn.f32x2, ptxas never auto-fuses).
// ---------------------------------------------------------------------------
typedef unsigned long long u64;

__device__ __forceinline__ u64 ffma2(u64 a, u64 b, u64 c) {
    u64 d;
    asm("fma.rn.f32x2 %0, %1, %2, %3;" : "=l"(d) : "l"(a), "l"(b), "l"(c));
    return d;
}
__device__ __forceinline__ u64 pack2(float x, float y) {
    u64 r;
    asm("mov.b64 %0, {%1, %2};" : "=l"(r) : "f"(x), "f"(y));
    return r;
}
__device__ __forceinline__ float2 unpack2(u64 v) {
    float2 r;
    asm("mov.b64 {%0, %1}, %2;" : "=f"(r.x), "=f"(r.y) : "l"(v));
    return r;
}

// ---------------------------------------------------------------------------
// Kernel 1: QKV projection. X[4096,768] @ W[768,2304] + bias,
// epilogue scatters into g_Q/g_K/g_V with head split [b][h][l][d].
// 128x128 tile, BK=8, 256 threads, 8x8 per thread, f32x2 inner loop.
// ---------------------------------------------------------------------------
__global__ __launch_bounds__(256) void qkv_gemm_kernel(
    const float* __restrict__ X, const float* __restrict__ W,
    const float* __restrict__ bias)
{
    __shared__ float As[8][128];
    __shared__ float Bs[8][128];
    const int tid = threadIdx.x;
    const int tx = tid & 15, ty = tid >> 4;
    const int row0 = blockIdx.y * 128;
    const int col0 = blockIdx.x * 128;

    u64 acc2[8][4];
    #pragma unroll
    for (int i = 0; i < 8; i++)
        #pragma unroll
        for (int j = 0; j < 4; j++) acc2[i][j] = 0ull;

    const int a_row = tid >> 1;         // 0..127
    const int a_col = (tid & 1) * 4;    // 0 or 4
    const int b_row = tid >> 5;         // 0..7
    const int b_col = (tid & 31) * 4;   // 0..124

    for (int k0 = 0; k0 < DD; k0 += 8) {
        float4 av = *(const float4*)(X + (size_t)(row0 + a_row) * DD + k0 + a_col);
        As[a_col + 0][a_row] = av.x;
        As[a_col + 1][a_row] = av.y;
        As[a_col + 2][a_row] = av.z;
        As[a_col + 3][a_row] = av.w;
        float4 bv = *(const float4*)(W + (size_t)(k0 + b_row) * ND3 + col0 + b_col);
        *(float4*)(&Bs[b_row][b_col]) = bv;
        __syncthreads();
        #pragma unroll
        for (int kk = 0; kk < 8; kk++) {
            float a[8];
            *(float4*)(a)     = *(const float4*)(&As[kk][ty * 8]);
            *(float4*)(a + 4) = *(const float4*)(&As[kk][ty * 8 + 4]);
            u64 b2[4];
            *(double2*)(b2)     = *(const double2*)(&Bs[kk][tx * 8]);
            *(double2*)(b2 + 2) = *(const double2*)(&Bs[kk][tx * 8 + 4]);
            #pragma unroll
            for (int i = 0; i < 8; i++) {
                const u64 a2 = pack2(a[i], a[i]);
                #pragma unroll
                for (int j = 0; j < 4; j++)
                    acc2[i][j] = ffma2(a2, b2[j], acc2[i][j]);
            }
        }
        __syncthreads();
    }

    // Epilogue: route to Q/K/V per-head layout
    #pragma unroll
    for (int i = 0; i < 8; i++) {
        const int r = row0 + ty * 8 + i;
        const int bb = r >> 11;        // /2048
        const int l  = r & 2047;
        float acc[8];
        #pragma unroll
        for (int j = 0; j < 4; j++) {
            float2 p = unpack2(acc2[i][j]);
            acc[2 * j] = p.x; acc[2 * j + 1] = p.y;
        }
        #pragma unroll
        for (int j = 0; j < 8; j++) {
            const int c = col0 + tx * 8 + j;
            float v = acc[j] + bias[c];
            const int which = c / DD;
            const int rem = c - which * DD;
            const int h = rem >> 6;
            const int d = rem & 63;
            const size_t dst = (((size_t)(bb * HH + h)) * LL + l) * HD + d;
            float* out = (which == 0) ? g_Q : (which == 1) ? g_K : g_V;
            out[dst] = v;
        }
    }
}

// ---------------------------------------------------------------------------
// Kernel 2: RoPE on Q and K in place. One thread per (b,h,l,t), t in [0,32).
// ---------------------------------------------------------------------------
__global__ __launch_bounds__(256) void rope_kernel()
{
    const int idx = blockIdx.x * blockDim.x + threadIdx.x;   // [0, B*H*L*32)
    const int t = idx & 31;
    const int l = (idx >> 5) & (LL - 1);
    const int bh = idx >> 16;  // / (32*2048)
    if (bh >= BB * HH) return;

    const float inv_freq = powf(10000.0f, -(float)t / 32.0f);
    const float angle = (float)l * inv_freq;
    const float c = cosf(angle);
    const float s = sinf(angle);

    const size_t base = ((size_t)bh * LL + l) * HD;
    {
        float x1 = g_Q[base + t], x2 = g_Q[base + t + 32];
        g_Q[base + t]      = x1 * c - x2 * s;
        g_Q[base + t + 32] = x2 * c + x1 * s;
    }
    {
        float x1 = g_K[base + t], x2 = g_K[base + t + 32];
        g_K[base + t]      = x1 * c - x2 * s;
        g_K[base + t + 32] = x2 * c + x1 * s;
    }
}

// ---------------------------------------------------------------------------
// Kernel 3: causal attention. Block = (qtile of 64, h, b). 256 threads.
// Streams 64-key tiles: S = Q K^T, p = exp(s/sqrt(L)) (no max-sub; scores
// are tiny), write unnormalized p to probs, accumulate O and row sums.
// f32x2 packed FMA in both the S and PV loops.
// ---------------------------------------------------------------------------
__global__ __launch_bounds__(256) void attn_kernel(float* __restrict__ probs)
{
    extern __shared__ float sm[];
    float* Qs = sm;          // Qs[d*64 + qi]
    float* Ks = sm + 4096;   // Ks[d*64 + kj]
    float* Vs = sm + 8192;   // Vs[k*64 + d]
    float* Ps = sm + 12288;  // Ps[qi*64 + kj]
    __shared__ float ls[64];

    const int tid = threadIdx.x;
    const int tx = tid & 15, ty = tid >> 4;
    const int q0 = blockIdx.x * 64;
    const int h = blockIdx.y, bb = blockIdx.z;
    const size_t bh = (size_t)bb * HH + h;

    const float* Qb = g_Q + (bh * LL + q0) * HD;
    const float* Kb = g_K + bh * LL * HD;
    const float* Vb = g_V + bh * LL * HD;
    float* Pb = probs + (bh * LL + q0) * LL;

    // Load Q tile transposed (d-major)
    #pragma unroll
    for (int t = 0; t < 4; t++) {
        int fi = tid + t * 256;             // float4 idx 0..1023
        int qi = fi >> 4;
        int d4 = (fi & 15) << 2;
        float4 v = *(const float4*)(Qb + qi * HD + d4);
        Qs[(d4 + 0) * 64 + qi] = v.x;
        Qs[(d4 + 1) * 64 + qi] = v.y;
        Qs[(d4 + 2) * 64 + qi] = v.z;
        Qs[(d4 + 3) * 64 + qi] = v.w;
    }
    if (tid < 64) ls[tid] = 0.f;

    u64 o2[4][2];
    #pragma unroll
    for (int i = 0; i < 4; i++) { o2[i][0] = 0ull; o2[i][1] = 0ull; }

    const float scale = rsqrtf(2048.0f);
    __syncthreads();

    const int ntiles = blockIdx.x + 1;  // key tiles with any unmasked entry
    for (int kt = 0; kt < 32; kt++) {
        const int k0 = kt * 64;
        if (kt >= ntiles) {
            // fully masked: write zeros (d_out is poisoned)
            float4 z = make_float4(0.f, 0.f, 0.f, 0.f);
            #pragma unroll
            for (int t = 0; t < 4; t++) {
                int fi = tid + t * 256;
                int qi = fi >> 4;
                int kg = (fi & 15) << 2;
                *(float4*)(Pb + (size_t)qi * LL + k0 + kg) = z;
            }
            continue;
        }

        // Load K (transposed) and V tiles
        #pragma unroll
        for (int t = 0; t < 4; t++) {
            int fi = tid + t * 256;
            int kj = fi >> 4;
            int d4 = (fi & 15) << 2;
            float4 v = *(const float4*)(Kb + (size_t)(k0 + kj) * HD + d4);
            Ks[(d4 + 0) * 64 + kj] = v.x;
            Ks[(d4 + 1) * 64 + kj] = v.y;
            Ks[(d4 + 2) * 64 + kj] = v.z;
            Ks[(d4 + 3) * 64 + kj] = v.w;
            float4 vv = *(const float4*)(Vb + (size_t)(k0 + kj) * HD + d4);
            *(float4*)(Vs + fi * 4) = vv;
        }
        __syncthreads();

        // S = Q K^T  (packed pairs over the 4 key columns)
        u64 s2[4][2];
        #pragma unroll
        for (int i = 0; i < 4; i++) { s2[i][0] = 0ull; s2[i][1] = 0ull; }
        #pragma unroll
        for (int d = 0; d < 64; d++) {
            float a[4];
            *(float4*)a = *(const float4*)(Qs + d * 64 + ty * 4);
            u64 b2[2];
            *(double2*)b2 = *(const double2*)(Ks + d * 64 + tx * 4);
            #pragma unroll
            for (int i = 0; i < 4; i++) {
                const u64 a2 = pack2(a[i], a[i]);
                s2[i][0] = ffma2(a2, b2[0], s2[i][0]);
                s2[i][1] = ffma2(a2, b2[1], s2[i][1]);
            }
        }

        // exp + causal mask -> Ps
        #pragma unroll
        for (int i = 0; i < 4; i++) {
            const int qg = q0 + ty * 4 + i;
            float s[4];
            float2 p0 = unpack2(s2[i][0]);
            float2 p1 = unpack2(s2[i][1]);
            s[0] = p0.x; s[1] = p0.y; s[2] = p1.x; s[3] = p1.y;
            #pragma unroll
            for (int j = 0; j < 4; j++) {
                const int kg = k0 + tx * 4 + j;
                float p = (kg <= qg) ? __expf(s[j] * scale) : 0.f;
                Ps[(ty * 4 + i) * 64 + tx * 4 + j] = p;
            }
        }
        __syncthreads();

        // row sums
        if (tid < 64) {
            float acc = 0.f;
            #pragma unroll 16
            for (int k = 0; k < 64; k++) acc += Ps[tid * 64 + k];
            ls[tid] += acc;
        }

        // write unnormalized probs (coalesced float4)
        #pragma unroll
        for (int t = 0; t < 4; t++) {
            int fi = tid + t * 256;
            int qi = fi >> 4;
            int kg = (fi & 15) << 2;
            *(float4*)(Pb + (size_t)qi * LL + k0 + kg) =
                *(const float4*)(Ps + qi * 64 + kg);
        }

        // O += P V  (packed pairs over the 4 d columns)
        #pragma unroll
        for (int k = 0; k < 64; k++) {
            u64 b2[2];
            *(double2*)b2 = *(const double2*)(Vs + k * 64 + tx * 4);
            #pragma unroll
            for (int i = 0; i < 4; i++) {
                const float av = Ps[(ty * 4 + i) * 64 + k];
                const u64 a2 = pack2(av, av);
                o2[i][0] = ffma2(a2, b2[0], o2[i][0]);
                o2[i][1] = ffma2(a2, b2[1], o2[i][1]);
            }
        }
        __syncthreads();
    }

    // Finalize: divide by row sums, write attn scratch [b][l][h*64+d]
    #pragma unroll
    for (int i = 0; i < 4; i++) {
        const int qi = ty * 4 + i;
        const float inv = 1.0f / ls[qi];
        float2 p0 = unpack2(o2[i][0]);
        float2 p1 = unpack2(o2[i][1]);
        float4 vv = make_float4(p0.x * inv, p0.y * inv, p1.x * inv, p1.y * inv);
        *(float4*)(g_attn + ((size_t)bb * LL + q0 + qi) * DD + h * HD + tx * 4) = vv;
    }
    if (tid < 64) g_lsum[bh * LL + q0 + tid] = ls[tid];
}

// ---------------------------------------------------------------------------
// Kernel 4: normalize probs in place by row sums. 2x float4 per thread
// for deeper MLP. Row = 512 f4; i is even so both f4 stay in one row.
// ---------------------------------------------------------------------------
__global__ __launch_bounds__(256) void norm_kernel(float* __restrict__ probs)
{
    const size_t i = ((size_t)blockIdx.x * blockDim.x + threadIdx.x) * 2;  // f4 idx
    const size_t row = i >> 9;  // / 512
    float4 v0 = ((float4*)probs)[i];
    float4 v1 = ((float4*)probs)[i + 1];
    const float inv = 1.0f / g_lsum[row];
    v0.x *= inv; v0.y *= inv; v0.z *= inv; v0.w *= inv;
    v1.x *= inv; v1.y *= inv; v1.z *= inv; v1.w *= inv;
    ((float4*)probs)[i]     = v0;
    ((float4*)probs)[i + 1] = v1;
}

// ---------------------------------------------------------------------------
// Kernel 5: output projection. g_attn[4096,768] @ w_out[768,768] + b_out.
// Same f32x2 SGEMM structure as kernel 1.
// ---------------------------------------------------------------------------
__global__ __launch_bounds__(256) void out_gemm_kernel(
    const float* __restrict__ W, const float* __restrict__ bias,
    float* __restrict__ out)
{
    __shared__ float As[8][128];
    __shared__ float Bs[8][128];
    const int tid = threadIdx.x;
    const int tx = tid & 15, ty = tid >> 4;
    const int row0 = blockIdx.y * 128;
    const int col0 = blockIdx.x * 128;

    u64 acc2[8][4];
    #pragma unroll
    for (int i = 0; i < 8; i++)
        #pragma unroll
        for (int j = 0; j < 4; j++) acc2[i][j] = 0ull;

    const int a_row = tid >> 1;
    const int a_col = (tid & 1) * 4;
    const int b_row = tid >> 5;
    const int b_col = (tid & 31) * 4;

    for (int k0 = 0; k0 < DD; k0 += 8) {
        float4 av = *(const float4*)(g_attn + (size_t)(row0 + a_row) * DD + k0 + a_col);
        As[a_col + 0][a_row] = av.x;
        As[a_col + 1][a_row] = av.y;
        As[a_col + 2][a_row] = av.z;
        As[a_col + 3][a_row] = av.w;
        float4 bv = *(const float4*)(W + (size_t)(k0 + b_row) * DD + col0 + b_col);
        *(float4*)(&Bs[b_row][b_col]) = bv;
        __syncthreads();
        #pragma unroll
        for (int kk = 0; kk < 8; kk++) {
            float a[8];
            *(float4*)(a)     = *(const float4*)(&As[kk][ty * 8]);
            *(float4*)(a + 4) = *(const float4*)(&As[kk][ty * 8 + 4]);
            u64 b2[4];
            *(double2*)(b2)     = *(const double2*)(&Bs[kk][tx * 8]);
            *(double2*)(b2 + 2) = *(const double2*)(&Bs[kk][tx * 8 + 4]);
            #pragma unroll
            for (int i = 0; i < 8; i++) {
                const u64 a2 = pack2(a[i], a[i]);
                #pragma unroll
                for (int j = 0; j < 4; j++)
                    acc2[i][j] = ffma2(a2, b2[j], acc2[i][j]);
            }
        }
        __syncthreads();
    }

    #pragma unroll
    for (int i = 0; i < 8; i++) {
        const int r = row0 + ty * 8 + i;
        float acc[8];
        #pragma unroll
        for (int j = 0; j < 4; j++) {
            float2 p = unpack2(acc2[i][j]);
            acc[2 * j] = p.x; acc[2 * j + 1] = p.y;
        }
        #pragma unroll
        for (int j = 0; j < 8; j += 4) {
            const int c = col0 + tx * 8 + j;
            float4 v = make_float4(acc[j + 0] + bias[c + 0],
                                   acc[j + 1] + bias[c + 1],
                                   acc[j + 2] + bias[c + 2],
                                   acc[j + 3] + bias[c + 3]);
            *(float4*)(out + (size_t)r * DD + c) = v;
        }
    }
}

// ---------------------------------------------------------------------------
extern "C" void kernel_launch(void* const* d_in, const int* in_sizes, int n_in,
                              void* d_out, int out_size)
{
    const float* X     = (const float*)d_in[0];  // [B,L,D]
    const float* w_qkv = (const float*)d_in[1];  // [D,3D]
    const float* b_qkv = (const float*)d_in[2];  // [3D]
    const float* w_out = (const float*)d_in[3];  // [D,D]
    const float* b_out = (const float*)d_in[4];  // [D]

    float* out   = (float*)d_out;                       // [B,L,D]
    float* probs = out + (size_t)BB * LL * DD;          // [B,H,L,L]

    // 1. QKV projection -> per-head Q/K/V
    qkv_gemm_kernel<<<dim3(ND3 / 128, (BB * LL) / 128), 256>>>(X, w_qkv, b_qkv);

    // 2. RoPE on Q,K
    rope_kernel<<<(BB * HH * LL * 32) / 256, 256>>>();

    // 3. Attention (dynamic smem 64KB)
    cudaFuncSetAttribute(attn_kernel,
                         cudaFuncAttributeMaxDynamicSharedMemorySize, 65536);
    attn_kernel<<<dim3(LL / 64, HH, BB), 256, 65536>>>(probs);

    // 4. Normalize probs (2 float4 per thread)
    norm_kernel<<<(int)(((size_t)BB * HH * LL * LL / 8) / 256), 256>>>(probs);

    // 5. Output projection
    out_gemm_kernel<<<dim3(DD / 128, (BB * LL) / 128), 256>>>(w_out, b_out, out);
}

// round 5
// speedup vs baseline: 1.3832x; 1.3264x over previous
#include <cuda_runtime.h>
#include <cuda_bf16.h>
#include <cstdint>
#include <math.h>

// Problem constants
#define BB 2
#define LL 2048
#define DD 768
#define HH 12
#define HD 64
#define ND3 2304   // 3*D
#define KDIM 768

typedef unsigned long long u64;
typedef unsigned int u32;

// Scratch (device globals: allocation-free rule)
__device__ float g_Q[BB * HH * LL * HD];
__device__ float g_K[BB * HH * LL * HD];
__device__ float g_V[BB * HH * LL * HD];
__device__ float g_attn[BB * LL * DD];
__device__ float g_lsum[BB * HH * LL];

// bf16 hi/lo split operands for HMMA GEMMs
__device__ __nv_bfloat16 gXhi[BB * LL * DD], gXlo[BB * LL * DD];
__device__ __nv_bfloat16 gWqkv_hi[ND3 * KDIM], gWqkv_lo[ND3 * KDIM];   // [N][K]
__device__ __nv_bfloat16 gWout_hi[DD * KDIM],  gWout_lo[DD * KDIM];    // [N][K]
__device__ __nv_bfloat16 gAhi[BB * LL * DD],   gAlo[BB * LL * DD];

// ---------------------------------------------------------------------------
// PTX helpers: mma.sync (sm_80+, compiles on plain compute_103) + ldmatrix
// ---------------------------------------------------------------------------
__device__ __forceinline__ u32 smem_u32(const void* p) {
    u32 a;
    asm("{ .reg .u64 t; cvta.to.shared.u64 t, %1; cvt.u32.u64 %0, t; }"
        : "=r"(a) : "l"(p));
    return a;
}
__device__ __forceinline__ void ldsm4(u32* r, u32 addr) {
    asm volatile("ldmatrix.sync.aligned.m8n8.x4.shared.b16 {%0,%1,%2,%3}, [%4];"
                 : "=r"(r[0]), "=r"(r[1]), "=r"(r[2]), "=r"(r[3]) : "r"(addr));
}
__device__ __forceinline__ void mma16816(float* c, const u32* a, const u32* b) {
    asm volatile(
        "mma.sync.aligned.m16n8k16.row.col.f32.bf16.bf16.f32 "
        "{%0,%1,%2,%3}, {%4,%5,%6,%7}, {%8,%9}, {%0,%1,%2,%3};"
        : "+f"(c[0]), "+f"(c[1]), "+f"(c[2]), "+f"(c[3])
        : "r"(a[0]), "r"(a[1]), "r"(a[2]), "r"(a[3]), "r"(b[0]), "r"(b[1]));
}

// Packed fp32x2 helpers (attention kernel)
__device__ __forceinline__ u64 ffma2(u64 a, u64 b, u64 c) {
    u64 d;
    asm("fma.rn.f32x2 %0, %1, %2, %3;" : "=l"(d) : "l"(a), "l"(b), "l"(c));
    return d;
}
__device__ __forceinline__ u64 pack2(float x, float y) {
    u64 r;
    asm("mov.b64 %0, {%1, %2};" : "=l"(r) : "f"(x), "f"(y));
    return r;
}
__device__ __forceinline__ float2 unpack2(u64 v) {
    float2 r;
    asm("mov.b64 {%0, %1}, %2;" : "=f"(r.x), "=f"(r.y) : "l"(v));
    return r;
}

// ---------------------------------------------------------------------------
// Conversion kernels: fp32 -> bf16 hi/lo split
// ---------------------------------------------------------------------------
__device__ __forceinline__ void split_bf16(float x, __nv_bfloat16& h, __nv_bfloat16& l) {
    h = __float2bfloat16(x);
    l = __float2bfloat16(x - __bfloat162float(h));
}

__global__ __launch_bounds__(256) void xconv_kernel(
    const float* __restrict__ src, __nv_bfloat16* __restrict__ hi,
    __nv_bfloat16* __restrict__ lo)
{
    const int i = blockIdx.x * 256 + threadIdx.x;
    __nv_bfloat16 h, l;
    split_bf16(src[i], h, l);
    hi[i] = h; lo[i] = l;
}

// W[K][N] row-major -> hi/lo[N][K] (transposed, bf16 split)
__global__ __launch_bounds__(256) void wconv_kernel(
    const float* __restrict__ W, __nv_bfloat16* __restrict__ hi,
    __nv_bfloat16* __restrict__ lo, int K, int N)
{
    __shared__ float t[32][33];
    const int n0 = blockIdx.x * 32, k0 = blockIdx.y * 32;
    const int tx = threadIdx.x, ty = threadIdx.y;   // 32 x 8
    #pragma unroll
    for (int i = 0; i < 4; i++)
        t[ty + 8 * i][tx] = W[(size_t)(k0 + ty + 8 * i) * N + n0 + tx];
    __syncthreads();
    #pragma unroll
    for (int i = 0; i < 4; i++) {
        const int n = n0 + ty + 8 * i, k = k0 + tx;
        float x = t[tx][ty + 8 * i];
        __nv_bfloat16 h, l;
        split_bf16(x, h, l);
        hi[(size_t)n * K + k] = h;
        lo[(size_t)n * K + k] = l;
    }
}

// ---------------------------------------------------------------------------
// HMMA GEMM mainloop (device function): acc[4][4][4] (fp32 frags) +=
// [Ahi+Alo](128xK, rows row0..) @ [Bhi+Blo]^T (B is [N][K], rows col0..)
// with 3-term bf16 split. 256 threads = 8 warps (2 m x 4 n), warp tile 64x32.
// Smem stride 40 bf16 = 80B: ldmatrix row starts hit distinct bank groups.
// ---------------------------------------------------------------------------
struct GemmSmem {
    __nv_bfloat16 A[2][128][40];
    __nv_bfloat16 B[2][128][40];
};

__device__ __forceinline__ void hmma_mainloop(
    const __nv_bfloat16* __restrict__ Ahi, const __nv_bfloat16* __restrict__ Alo,
    const __nv_bfloat16* __restrict__ Bhi, const __nv_bfloat16* __restrict__ Blo,
    GemmSmem& sm, int row0, int col0, float acc[4][4][4])
{
    const int tid = threadIdx.x;
    const int lane = tid & 31, wid = tid >> 5;
    const int warp_m = wid & 1, warp_n = wid >> 1;

    for (int kt = 0; kt < KDIM / 32; kt++) {
        // Stage 128x32 slices of all four matrices
        #pragma unroll
        for (int t = 0; t < 2; t++) {
            const int idx = tid + t * 256;           // 0..511
            const int r = idx >> 2, c4 = idx & 3;    // 4 x uint4 per row
            const size_t ga = (size_t)(row0 + r) * KDIM + kt * 32 + c4 * 8;
            const size_t gb = (size_t)(col0 + r) * KDIM + kt * 32 + c4 * 8;
            *(uint4*)&sm.A[0][r][c4 * 8] = *(const uint4*)(Ahi + ga);
            *(uint4*)&sm.A[1][r][c4 * 8] = *(const uint4*)(Alo + ga);
            *(uint4*)&sm.B[0][r][c4 * 8] = *(const uint4*)(Bhi + gb);
            *(uint4*)&sm.B[1][r][c4 * 8] = *(const uint4*)(Blo + gb);
        }
        __syncthreads();

        #pragma unroll
        for (int ks = 0; ks < 2; ks++) {
            // A fragments: one ldmatrix.x4 per (mtile, hi/lo) = full 16x16
            u32 afh[4][4], afl[4][4];
            #pragma unroll
            for (int mt = 0; mt < 4; mt++) {
                const int mrow = warp_m * 64 + mt * 16 + (lane & 15);
                const int kcol = ks * 16 + (lane >> 4) * 8;
                ldsm4(afh[mt], smem_u32(&sm.A[0][mrow][kcol]));
                ldsm4(afl[mt], smem_u32(&sm.A[1][mrow][kcol]));
            }
            // B fragments: one ldmatrix.x4 covers 2 ntiles (b0,b1 each)
            u32 bfh[2][4], bfl[2][4];
            #pragma unroll
            for (int np = 0; np < 2; np++) {
                const int nrow = warp_n * 32 + np * 16 + ((lane >> 4) << 3) + (lane & 7);
                const int kcol = ks * 16 + ((lane >> 3) & 1) * 8;
                ldsm4(bfh[np], smem_u32(&sm.B[0][nrow][kcol]));
                ldsm4(bfl[np], smem_u32(&sm.B[1][nrow][kcol]));
            }
            #pragma unroll
            for (int mt = 0; mt < 4; mt++) {
                #pragma unroll
                for (int nt = 0; nt < 4; nt++) {
                    const u32* bh = &bfh[nt >> 1][(nt & 1) * 2];
                    const u32* bl = &bfl[nt >> 1][(nt & 1) * 2];
                    mma16816(acc[mt][nt], afh[mt], bh);   // hi*hi
                    mma16816(acc[mt][nt], afh[mt], bl);   // hi*lo
                    mma16816(acc[mt][nt], afl[mt], bh);   // lo*hi
                }
            }
        }
        __syncthreads();
    }
}

// ---------------------------------------------------------------------------
// Kernel: QKV projection via HMMA. Grid (18, 32). Epilogue adds bias and
// scatters fragments into per-head Q/K/V layout.
// ---------------------------------------------------------------------------
__global__ __launch_bounds__(256) void qkv_mma_kernel(const float* __restrict__ bias)
{
    __shared__ GemmSmem sm;
    const int tid = threadIdx.x;
    const int lane = tid & 31, wid = tid >> 5;
    const int warp_m = wid & 1, warp_n = wid >> 1;
    const int row0 = blockIdx.y * 128, col0 = blockIdx.x * 128;

    float acc[4][4][4];
    #pragma unroll
    for (int i = 0; i < 4; i++)
        #pragma unroll
        for (int j = 0; j < 4; j++)
            #pragma unroll
            for (int k = 0; k < 4; k++) acc[i][j][k] = 0.f;

    hmma_mainloop(gXhi, gXlo, gWqkv_hi, gWqkv_lo, sm, row0, col0, acc);

    #pragma unroll
    for (int mt = 0; mt < 4; mt++) {
        #pragma unroll
        for (int nt = 0; nt < 4; nt++) {
            const int c = col0 + warp_n * 32 + nt * 8 + (lane & 3) * 2;
            const int which = c / DD;
            const int rem = c - which * DD;
            const int h = rem >> 6, d = rem & 63;
            float* dst = (which == 0) ? g_Q : (which == 1) ? g_K : g_V;
            const float b0 = bias[c], b1 = bias[c + 1];
            #pragma unroll
            for (int half = 0; half < 2; half++) {
                const int r = row0 + warp_m * 64 + mt * 16 + (lane >> 2) + half * 8;
                const int bb = r >> 11, l = r & 2047;
                float2 v = make_float2(acc[mt][nt][half * 2] + b0,
                                       acc[mt][nt][half * 2 + 1] + b1);
                *(float2*)(dst + (((size_t)(bb * HH + h)) * LL + l) * HD + d) = v;
            }
        }
    }
}

// ---------------------------------------------------------------------------
// Kernel: output projection via HMMA. Grid (6, 32).
// ---------------------------------------------------------------------------
__global__ __launch_bounds__(256) void out_mma_kernel(
    const float* __restrict__ bias, float* __restrict__ out)
{
    __shared__ GemmSmem sm;
    const int tid = threadIdx.x;
    const int lane = tid & 31, wid = tid >> 5;
    const int warp_m = wid & 1, warp_n = wid >> 1;
    const int row0 = blockIdx.y * 128, col0 = blockIdx.x * 128;

    float acc[4][4][4];
    #pragma unroll
    for (int i = 0; i < 4; i++)
        #pragma unroll
        for (int j = 0; j < 4; j++)
            #pragma unroll
            for (int k = 0; k < 4; k++) acc[i][j][k] = 0.f;

    hmma_mainloop(gAhi, gAlo, gWout_hi, gWout_lo, sm, row0, col0, acc);

    #pragma unroll
    for (int mt = 0; mt < 4; mt++) {
        #pragma unroll
        for (int nt = 0; nt < 4; nt++) {
            const int c = col0 + warp_n * 32 + nt * 8 + (lane & 3) * 2;
            const float b0 = bias[c], b1 = bias[c + 1];
            #pragma unroll
            for (int half = 0; half < 2; half++) {
                const int r = row0 + warp_m * 64 + mt * 16 + (lane >> 2) + half * 8;
                float2 v = make_float2(acc[mt][nt][half * 2] + b0,
                                       acc[mt][nt][half * 2 + 1] + b1);
                *(float2*)(out + (size_t)r * DD + c) = v;
            }
        }
    }
}

// ---------------------------------------------------------------------------
// Kernel: RoPE on Q and K in place.
// ---------------------------------------------------------------------------
__global__ __launch_bounds__(256) void rope_kernel()
{
    const int idx = blockIdx.x * blockDim.x + threadIdx.x;
    const int t = idx & 31;
    const int l = (idx >> 5) & (LL - 1);
    const int bh = idx >> 16;
    if (bh >= BB * HH) return;

    const float inv_freq = powf(10000.0f, -(float)t / 32.0f);
    const float angle = (float)l * inv_freq;
    const float c = cosf(angle);
    const float s = sinf(angle);

    const size_t base = ((size_t)bh * LL + l) * HD;
    {
        float x1 = g_Q[base + t], x2 = g_Q[base + t + 32];
        g_Q[base + t]      = x1 * c - x2 * s;
        g_Q[base + t + 32] = x2 * c + x1 * s;
    }
    {
        float x1 = g_K[base + t], x2 = g_K[base + t + 32];
        g_K[base + t]      = x1 * c - x2 * s;
        g_K[base + t + 32] = x2 * c + x1 * s;
    }
}

// ---------------------------------------------------------------------------
// Kernel: causal attention (fp32 + f32x2 packed FMA, unchanged from R2).
// ---------------------------------------------------------------------------
__global__ __launch_bounds__(256) void attn_kernel(float* __restrict__ probs)
{
    extern __shared__ float smf[];
    float* Qs = smf;
    float* Ks = smf + 4096;
    float* Vs = smf + 8192;
    float* Ps = smf + 12288;
    __shared__ float ls[64];

    const int tid = threadIdx.x;
    const int tx = tid & 15, ty = tid >> 4;
    const int q0 = blockIdx.x * 64;
    const int h = blockIdx.y, bb = blockIdx.z;
    const size_t bh = (size_t)bb * HH + h;

    const float* Qb = g_Q + (bh * LL + q0) * HD;
    const float* Kb = g_K + bh * LL * HD;
    const float* Vb = g_V + bh * LL * HD;
    float* Pb = probs + (bh * LL + q0) * LL;

    #pragma unroll
    for (int t = 0; t < 4; t++) {
        int fi = tid + t * 256;
        int qi = fi >> 4;
        int d4 = (fi & 15) << 2;
        float4 v = *(const float4*)(Qb + qi * HD + d4);
        Qs[(d4 + 0) * 64 + qi] = v.x;
        Qs[(d4 + 1) * 64 + qi] = v.y;
        Qs[(d4 + 2) * 64 + qi] = v.z;
        Qs[(d4 + 3) * 64 + qi] = v.w;
    }
    if (tid < 64) ls[tid] = 0.f;

    u64 o2[4][2];
    #pragma unroll
    for (int i = 0; i < 4; i++) { o2[i][0] = 0ull; o2[i][1] = 0ull; }

    const float scale = rsqrtf(2048.0f);
    __syncthreads();

    const int ntiles = blockIdx.x + 1;
    for (int kt = 0; kt < 32; kt++) {
        const int k0 = kt * 64;
        if (kt >= ntiles) {
            float4 z = make_float4(0.f, 0.f, 0.f, 0.f);
            #pragma unroll
            for (int t = 0; t < 4; t++) {
                int fi = tid + t * 256;
                int qi = fi >> 4;
                int kg = (fi & 15) << 2;
                *(float4*)(Pb + (size_t)qi * LL + k0 + kg) = z;
            }
            continue;
        }

        #pragma unroll
        for (int t = 0; t < 4; t++) {
            int fi = tid + t * 256;
            int kj = fi >> 4;
            int d4 = (fi & 15) << 2;
            float4 v = *(const float4*)(Kb + (size_t)(k0 + kj) * HD + d4);
            Ks[(d4 + 0) * 64 + kj] = v.x;
            Ks[(d4 + 1) * 64 + kj] = v.y;
            Ks[(d4 + 2) * 64 + kj] = v.z;
            Ks[(d4 + 3) * 64 + kj] = v.w;
            float4 vv = *(const float4*)(Vb + (size_t)(k0 + kj) * HD + d4);
            *(float4*)(Vs + fi * 4) = vv;
        }
        __syncthreads();

        u64 s2[4][2];
        #pragma unroll
        for (int i = 0; i < 4; i++) { s2[i][0] = 0ull; s2[i][1] = 0ull; }
        #pragma unroll
        for (int d = 0; d < 64; d++) {
            float a[4];
            *(float4*)a = *(const float4*)(Qs + d * 64 + ty * 4);
            u64 b2[2];
            *(double2*)b2 = *(const double2*)(Ks + d * 64 + tx * 4);
            #pragma unroll
            for (int i = 0; i < 4; i++) {
                const u64 a2 = pack2(a[i], a[i]);
                s2[i][0] = ffma2(a2, b2[0], s2[i][0]);
                s2[i][1] = ffma2(a2, b2[1], s2[i][1]);
            }
        }

        #pragma unroll
        for (int i = 0; i < 4; i++) {
            const int qg = q0 + ty * 4 + i;
            float s[4];
            float2 p0 = unpack2(s2[i][0]);
            float2 p1 = unpack2(s2[i][1]);
            s[0] = p0.x; s[1] = p0.y; s[2] = p1.x; s[3] = p1.y;
            #pragma unroll
            for (int j = 0; j < 4; j++) {
                const int kg = k0 + tx * 4 + j;
                float p = (kg <= qg) ? __expf(s[j] * scale) : 0.f;
                Ps[(ty * 4 + i) * 64 + tx * 4 + j] = p;
            }
        }
        __syncthreads();

        if (tid < 64) {
            float acc = 0.f;
            #pragma unroll 16
            for (int k = 0; k < 64; k++) acc += Ps[tid * 64 + k];
            ls[tid] += acc;
        }

        #pragma unroll
        for (int t = 0; t < 4; t++) {
            int fi = tid + t * 256;
            int qi = fi >> 4;
            int kg = (fi & 15) << 2;
            *(float4*)(Pb + (size_t)qi * LL + k0 + kg) =
                *(const float4*)(Ps + qi * 64 + kg);
        }

        #pragma unroll
        for (int k = 0; k < 64; k++) {
            u64 b2[2];
            *(double2*)b2 = *(const double2*)(Vs + k * 64 + tx * 4);
            #pragma unroll
            for (int i = 0; i < 4; i++) {
                const float av = Ps[(ty * 4 + i) * 64 + k];
                const u64 a2 = pack2(av, av);
                o2[i][0] = ffma2(a2, b2[0], o2[i][0]);
                o2[i][1] = ffma2(a2, b2[1], o2[i][1]);
            }
        }
        __syncthreads();
    }

    #pragma unroll
    for (int i = 0; i < 4; i++) {
        const int qi = ty * 4 + i;
        const float inv = 1.0f / ls[qi];
        float2 p0 = unpack2(o2[i][0]);
        float2 p1 = unpack2(o2[i][1]);
        float4 vv = make_float4(p0.x * inv, p0.y * inv, p1.x * inv, p1.y * inv);
        *(float4*)(g_attn + ((size_t)bb * LL + q0 + qi) * DD + h * HD + tx * 4) = vv;
    }
    if (tid < 64) g_lsum[bh * LL + q0 + tid] = ls[tid];
}

// ---------------------------------------------------------------------------
// Kernel: convert attention output to bf16 hi/lo for the out projection
// ---------------------------------------------------------------------------
__global__ __launch_bounds__(256) void aconv_kernel()
{
    const int i = blockIdx.x * 256 + threadIdx.x;
    __nv_bfloat16 h, l;
    split_bf16(g_attn[i], h, l);
    gAhi[i] = h; gAlo[i] = l;
}

// ---------------------------------------------------------------------------
// Kernel: normalize probs in place by row sums. 2x float4 per thread.
// ---------------------------------------------------------------------------
__global__ __launch_bounds__(256) void norm_kernel(float* __restrict__ probs)
{
    const size_t i = ((size_t)blockIdx.x * blockDim.x + threadIdx.x) * 2;
    const size_t row = i >> 9;
    float4 v0 = ((float4*)probs)[i];
    float4 v1 = ((float4*)probs)[i + 1];
    const float inv = 1.0f / g_lsum[row];
    v0.x *= inv; v0.y *= inv; v0.z *= inv; v0.w *= inv;
    v1.x *= inv; v1.y *= inv; v1.z *= inv; v1.w *= inv;
    ((float4*)probs)[i]     = v0;
    ((float4*)probs)[i + 1] = v1;
}

// ---------------------------------------------------------------------------
extern "C" void kernel_launch(void* const* d_in, const int* in_sizes, int n_in,
                              void* d_out, int out_size)
{
    const float* X     = (const float*)d_in[0];
    const float* w_qkv = (const float*)d_in[1];
    const float* b_qkv = (const float*)d_in[2];
    const float* w_out = (const float*)d_in[3];
    const float* b_out = (const float*)d_in[4];

    float* out   = (float*)d_out;
    float* probs = out + (size_t)BB * LL * DD;

    __nv_bfloat16 *xhi, *xlo, *wqh, *wql, *woh, *wol;
    cudaGetSymbolAddress((void**)&xhi, gXhi);
    cudaGetSymbolAddress((void**)&xlo, gXlo);
    cudaGetSymbolAddress((void**)&wqh, gWqkv_hi);
    cudaGetSymbolAddress((void**)&wql, gWqkv_lo);
    cudaGetSymbolAddress((void**)&woh, gWout_hi);
    cudaGetSymbolAddress((void**)&wol, gWout_lo);

    cudaFuncSetAttribute(attn_kernel,
                         cudaFuncAttributeMaxDynamicSharedMemorySize, 65536);

    // 0. fp32 -> bf16 hi/lo conversions (X and both weight matrices)
    xconv_kernel<<<(BB * LL * DD) / 256, 256>>>(X, xhi, xlo);
    wconv_kernel<<<dim3(ND3 / 32, KDIM / 32), dim3(32, 8)>>>(w_qkv, wqh, wql, KDIM, ND3);
    wconv_kernel<<<dim3(DD / 32, KDIM / 32), dim3(32, 8)>>>(w_out, woh, wol, KDIM, DD);

    // 1. QKV projection (HMMA mma.sync)
    qkv_mma_kernel<<<dim3(ND3 / 128, (BB * LL) / 128), 256>>>(b_qkv);

    // 2. RoPE
    rope_kernel<<<(BB * HH * LL * 32) / 256, 256>>>();

    // 3. Attention
    attn_kernel<<<dim3(LL / 64, HH, BB), 256, 65536>>>(probs);

    // 4. Convert attention output for out projection
    aconv_kernel<<<(BB * LL * DD) / 256, 256>>>();

    // 5. Normalize probs
    norm_kernel<<<(int)(((size_t)BB * HH * LL * LL / 8) / 256), 256>>>(probs);

    // 6. Output projection (HMMA mma.sync)
    out_mma_kernel<<<dim3(DD / 128, (BB * LL) / 128), 256>>>(b_out, out);
}

// round 7
// speedup vs baseline: 2.1934x; 1.5857x over previous
#include <cuda_runtime.h>
#include <cuda_bf16.h>
#include <cstdint>
#include <math.h>

// Problem constants
#define BB 2
#define LL 2048
#define DD 768
#define HH 12
#define HD 64
#define ND3 2304   // 3*D
#define KDIM 768

typedef unsigned long long u64;
typedef unsigned int u32;

// Scratch (device globals: allocation-free rule)
__device__ float g_Q[BB * HH * LL * HD];
__device__ float g_K[BB * HH * LL * HD];
__device__ float g_V[BB * HH * LL * HD];
__device__ float g_lsum[BB * HH * LL];

// bf16 hi/lo split operands
__device__ __nv_bfloat16 gXhi[BB * LL * DD], gXlo[BB * LL * DD];
__device__ __nv_bfloat16 gWqkv_hi[ND3 * KDIM], gWqkv_lo[ND3 * KDIM];   // [N][K]
__device__ __nv_bfloat16 gWout_hi[DD * KDIM],  gWout_lo[DD * KDIM];    // [N][K]
__device__ __nv_bfloat16 gAhi[BB * LL * DD],   gAlo[BB * LL * DD];
// RoPE'd Q/K, [b][h][l][d]
__device__ __nv_bfloat16 gQhi[BB * HH * LL * HD], gQlo[BB * HH * LL * HD];
__device__ __nv_bfloat16 gKhi[BB * HH * LL * HD], gKlo[BB * HH * LL * HD];
// V transposed, [b][h][d][l]
__device__ __nv_bfloat16 gVthi[BB * HH * HD * LL], gVtlo[BB * HH * HD * LL];

// ---------------------------------------------------------------------------
// PTX helpers: mma.sync (sm_80+) + ldmatrix
// ---------------------------------------------------------------------------
__device__ __forceinline__ u32 smem_u32(const void* p) {
    u32 a;
    asm("{ .reg .u64 t; cvta.to.shared.u64 t, %1; cvt.u32.u64 %0, t; }"
        : "=r"(a) : "l"(p));
    return a;
}
__device__ __forceinline__ void ldsm4(u32* r, u32 addr) {
    asm volatile("ldmatrix.sync.aligned.m8n8.x4.shared.b16 {%0,%1,%2,%3}, [%4];"
                 : "=r"(r[0]), "=r"(r[1]), "=r"(r[2]), "=r"(r[3]) : "r"(addr));
}
__device__ __forceinline__ void mma16816(float* c, const u32* a, const u32* b) {
    asm volatile(
        "mma.sync.aligned.m16n8k16.row.col.f32.bf16.bf16.f32 "
        "{%0,%1,%2,%3}, {%4,%5,%6,%7}, {%8,%9}, {%0,%1,%2,%3};"
        : "+f"(c[0]), "+f"(c[1]), "+f"(c[2]), "+f"(c[3])
        : "r"(a[0]), "r"(a[1]), "r"(a[2]), "r"(a[3]), "r"(b[0]), "r"(b[1]));
}

__device__ __forceinline__ void split_bf16(float x, __nv_bfloat16& h, __nv_bfloat16& l) {
    h = __float2bfloat16(x);
    l = __float2bfloat16(x - __bfloat162float(h));
}

// ---------------------------------------------------------------------------
// Conversion kernels
// ---------------------------------------------------------------------------
__global__ __launch_bounds__(256) void xconv_kernel(
    const float* __restrict__ src, __nv_bfloat16* __restrict__ hi,
    __nv_bfloat16* __restrict__ lo)
{
    const int i = blockIdx.x * 256 + threadIdx.x;
    __nv_bfloat16 h, l;
    split_bf16(src[i], h, l);
    hi[i] = h; lo[i] = l;
}

// W[K][N] row-major -> hi/lo[N][K] (transposed, bf16 split)
__global__ __launch_bounds__(256) void wconv_kernel(
    const float* __restrict__ W, __nv_bfloat16* __restrict__ hi,
    __nv_bfloat16* __restrict__ lo, int K, int N)
{
    __shared__ float t[32][33];
    const int n0 = blockIdx.x * 32, k0 = blockIdx.y * 32;
    const int tx = threadIdx.x, ty = threadIdx.y;   // 32 x 8
    #pragma unroll
    for (int i = 0; i < 4; i++)
        t[ty + 8 * i][tx] = W[(size_t)(k0 + ty + 8 * i) * N + n0 + tx];
    __syncthreads();
    #pragma unroll
    for (int i = 0; i < 4; i++) {
        const int n = n0 + ty + 8 * i, k = k0 + tx;
        float x = t[tx][ty + 8 * i];
        __nv_bfloat16 h, l;
        split_bf16(x, h, l);
        hi[(size_t)n * K + k] = h;
        lo[(size_t)n * K + k] = l;
    }
}

// g_V [bh][l][64] fp32 -> gVt hi/lo [bh][64][LL] bf16 (transpose + split)
__global__ void vconv_kernel()   // grid (LL/32, HD/32, BH), block (32,8)
{
    __shared__ float t[32][33];
    const int l0 = blockIdx.x * 32, d0 = blockIdx.y * 32;
    const int bh = blockIdx.z;
    const int tx = threadIdx.x, ty = threadIdx.y;
    const float* V = g_V + (size_t)bh * LL * HD;
    #pragma unroll
    for (int i = 0; i < 4; i++)
        t[ty + 8 * i][tx] = V[(size_t)(l0 + ty + 8 * i) * HD + d0 + tx];
    __syncthreads();
    #pragma unroll
    for (int i = 0; i < 4; i++) {
        const int d = d0 + ty + 8 * i, l = l0 + tx;
        float x = t[tx][ty + 8 * i];
        __nv_bfloat16 h, lo_;
        split_bf16(x, h, lo_);
        const size_t o = (size_t)bh * HD * LL + (size_t)d * LL + l;
        gVthi[o] = h;
        gVtlo[o] = lo_;
    }
}

// ---------------------------------------------------------------------------
// HMMA GEMM mainloop (as R5, validated)
// ---------------------------------------------------------------------------
struct GemmSmem {
    __nv_bfloat16 A[2][128][40];
    __nv_bfloat16 B[2][128][40];
};

__device__ __forceinline__ void hmma_mainloop(
    const __nv_bfloat16* __restrict__ Ahi, const __nv_bfloat16* __restrict__ Alo,
    const __nv_bfloat16* __restrict__ Bhi, const __nv_bfloat16* __restrict__ Blo,
    GemmSmem& sm, int row0, int col0, float acc[4][4][4])
{
    const int tid = threadIdx.x;
    const int lane = tid & 31, wid = tid >> 5;
    const int warp_m = wid & 1, warp_n = wid >> 1;

    for (int kt = 0; kt < KDIM / 32; kt++) {
        #pragma unroll
        for (int t = 0; t < 2; t++) {
            const int idx = tid + t * 256;
            const int r = idx >> 2, c4 = idx & 3;
            const size_t ga = (size_t)(row0 + r) * KDIM + kt * 32 + c4 * 8;
            const size_t gb = (size_t)(col0 + r) * KDIM + kt * 32 + c4 * 8;
            *(uint4*)&sm.A[0][r][c4 * 8] = *(const uint4*)(Ahi + ga);
            *(uint4*)&sm.A[1][r][c4 * 8] = *(const uint4*)(Alo + ga);
            *(uint4*)&sm.B[0][r][c4 * 8] = *(const uint4*)(Bhi + gb);
            *(uint4*)&sm.B[1][r][c4 * 8] = *(const uint4*)(Blo + gb);
        }
        __syncthreads();

        #pragma unroll
        for (int ks = 0; ks < 2; ks++) {
            u32 afh[4][4], afl[4][4];
            #pragma unroll
            for (int mt = 0; mt < 4; mt++) {
                const int mrow = warp_m * 64 + mt * 16 + (lane & 15);
                const int kcol = ks * 16 + (lane >> 4) * 8;
                ldsm4(afh[mt], smem_u32(&sm.A[0][mrow][kcol]));
                ldsm4(afl[mt], smem_u32(&sm.A[1][mrow][kcol]));
            }
            u32 bfh[2][4], bfl[2][4];
            #pragma unroll
            for (int np = 0; np < 2; np++) {
                const int nrow = warp_n * 32 + np * 16 + ((lane >> 4) << 3) + (lane & 7);
                const int kcol = ks * 16 + ((lane >> 3) & 1) * 8;
                ldsm4(bfh[np], smem_u32(&sm.B[0][nrow][kcol]));
                ldsm4(bfl[np], smem_u32(&sm.B[1][nrow][kcol]));
            }
            #pragma unroll
            for (int mt = 0; mt < 4; mt++) {
                #pragma unroll
                for (int nt = 0; nt < 4; nt++) {
                    const u32* bh = &bfh[nt >> 1][(nt & 1) * 2];
                    const u32* bl = &bfl[nt >> 1][(nt & 1) * 2];
                    mma16816(acc[mt][nt], afh[mt], bh);
                    mma16816(acc[mt][nt], afh[mt], bl);
                    mma16816(acc[mt][nt], afl[mt], bh);
                }
            }
        }
        __syncthreads();
    }
}

// ---------------------------------------------------------------------------
// Kernel: QKV projection via HMMA. Epilogue scatters into per-head fp32 Q/K/V.
// ---------------------------------------------------------------------------
__global__ __launch_bounds__(256) void qkv_mma_kernel(const float* __restrict__ bias)
{
    __shared__ GemmSmem sm;
    const int tid = threadIdx.x;
    const int lane = tid & 31, wid = tid >> 5;
    const int warp_m = wid & 1, warp_n = wid >> 1;
    const int row0 = blockIdx.y * 128, col0 = blockIdx.x * 128;

    float acc[4][4][4];
    #pragma unroll
    for (int i = 0; i < 4; i++)
        #pragma unroll
        for (int j = 0; j < 4; j++)
            #pragma unroll
            for (int k = 0; k < 4; k++) acc[i][j][k] = 0.f;

    hmma_mainloop(gXhi, gXlo, gWqkv_hi, gWqkv_lo, sm, row0, col0, acc);

    #pragma unroll
    for (int mt = 0; mt < 4; mt++) {
        #pragma unroll
        for (int nt = 0; nt < 4; nt++) {
            const int c = col0 + warp_n * 32 + nt * 8 + (lane & 3) * 2;
            const int which = c / DD;
            const int rem = c - which * DD;
            const int h = rem >> 6, d = rem & 63;
            float* dst = (which == 0) ? g_Q : (which == 1) ? g_K : g_V;
            const float b0 = bias[c], b1 = bias[c + 1];
            #pragma unroll
            for (int half = 0; half < 2; half++) {
                const int r = row0 + warp_m * 64 + mt * 16 + (lane >> 2) + half * 8;
                const int bb = r >> 11, l = r & 2047;
                float2 v = make_float2(acc[mt][nt][half * 2] + b0,
                                       acc[mt][nt][half * 2 + 1] + b1);
                *(float2*)(dst + (((size_t)(bb * HH + h)) * LL + l) * HD + d) = v;
            }
        }
    }
}

// ---------------------------------------------------------------------------
// Kernel: output projection via HMMA.
// ---------------------------------------------------------------------------
__global__ __launch_bounds__(256) void out_mma_kernel(
    const float* __restrict__ bias, float* __restrict__ out)
{
    __shared__ GemmSmem sm;
    const int tid = threadIdx.x;
    const int lane = tid & 31, wid = tid >> 5;
    const int warp_m = wid & 1, warp_n = wid >> 1;
    const int row0 = blockIdx.y * 128, col0 = blockIdx.x * 128;

    float acc[4][4][4];
    #pragma unroll
    for (int i = 0; i < 4; i++)
        #pragma unroll
        for (int j = 0; j < 4; j++)
            #pragma unroll
            for (int k = 0; k < 4; k++) acc[i][j][k] = 0.f;

    hmma_mainloop(gAhi, gAlo, gWout_hi, gWout_lo, sm, row0, col0, acc);

    #pragma unroll
    for (int mt = 0; mt < 4; mt++) {
        #pragma unroll
        for (int nt = 0; nt < 4; nt++) {
            const int c = col0 + warp_n * 32 + nt * 8 + (lane & 3) * 2;
            const float b0 = bias[c], b1 = bias[c + 1];
            #pragma unroll
            for (int half = 0; half < 2; half++) {
                const int r = row0 + warp_m * 64 + mt * 16 + (lane >> 2) + half * 8;
                float2 v = make_float2(acc[mt][nt][half * 2] + b0,
                                       acc[mt][nt][half * 2 + 1] + b1);
                *(float2*)(out + (size_t)r * DD + c) = v;
            }
        }
    }
}

// ---------------------------------------------------------------------------
// Kernel: RoPE. fp32 Q/K in -> rotated bf16 hi/lo out.
// ---------------------------------------------------------------------------
__global__ __launch_bounds__(256) void rope_kernel()
{
    const int idx = blockIdx.x * blockDim.x + threadIdx.x;
    const int t = idx & 31;
    const int l = (idx >> 5) & (LL - 1);
    const int bh = idx >> 16;
    if (bh >= BB * HH) return;

    const float inv_freq = powf(10000.0f, -(float)t / 32.0f);
    const float angle = (float)l * inv_freq;
    const float c = cosf(angle);
    const float s = sinf(angle);

    const size_t base = ((size_t)bh * LL + l) * HD;
    {
        float x1 = g_Q[base + t], x2 = g_Q[base + t + 32];
        float y1 = x1 * c - x2 * s, y2 = x2 * c + x1 * s;
        __nv_bfloat16 h1, l1, h2, l2;
        split_bf16(y1, h1, l1); split_bf16(y2, h2, l2);
        gQhi[base + t] = h1;      gQlo[base + t] = l1;
        gQhi[base + t + 32] = h2; gQlo[base + t + 32] = l2;
    }
    {
        float x1 = g_K[base + t], x2 = g_K[base + t + 32];
        float y1 = x1 * c - x2 * s, y2 = x2 * c + x1 * s;
        __nv_bfloat16 h1, l1, h2, l2;
        split_bf16(y1, h1, l1); split_bf16(y2, h2, l2);
        gKhi[base + t] = h1;      gKlo[base + t] = l1;
        gKhi[base + t + 32] = h2; gKlo[base + t + 32] = l2;
    }
}

// ---------------------------------------------------------------------------
// Kernel: fused causal attention on HMMA. Block = (qtile 128, h, b), 8 warps.
// S phase: warps 2x4 over S(128x128). PV phase: warps 4x2 over O(128x64).
// P routed through smem as bf16 hi/lo; probs written unnormalized (norm pass
// divides by g_lsum). O written directly as bf16 hi/lo into gAhi/gAlo.
// ---------------------------------------------------------------------------
struct AttnSmem {
    __nv_bfloat16 Qhi[128][72], Qlo[128][72];
    __nv_bfloat16 Khi[128][72], Klo[128][72];
    __nv_bfloat16 Vthi[64][136], Vtlo[64][136];
    __nv_bfloat16 Phi[128][136], Plo[128][136];
    float ls[128];
};

__global__ __launch_bounds__(256) void attn_mma_kernel(float* __restrict__ probs)
{
    extern __shared__ char smraw[];
    AttnSmem& sm = *(AttnSmem*)smraw;
    const int tid = threadIdx.x, lane = tid & 31, wid = tid >> 5;
    const int warp_m = wid & 1, warp_n = wid >> 1;     // S phase 2x4
    const int warp_om = wid & 3, warp_on = wid >> 2;   // PV phase 4x2
    const int qt = blockIdx.x, h = blockIdx.y, bb = blockIdx.z;
    const int q0 = qt * 128;
    const size_t bh = (size_t)bb * HH + h;

    const __nv_bfloat16* Qhig = gQhi + (bh * LL + q0) * HD;
    const __nv_bfloat16* Qlog = gQlo + (bh * LL + q0) * HD;
    const __nv_bfloat16* Khig = gKhi + bh * LL * HD;
    const __nv_bfloat16* Klog = gKlo + bh * LL * HD;
    const __nv_bfloat16* Vthig = gVthi + bh * HD * LL;
    const __nv_bfloat16* Vtlog = gVtlo + bh * HD * LL;
    float* Pb = probs + (bh * LL + q0) * LL;

    // Stage Q tile (resident all kernel)
    #pragma unroll
    for (int t = 0; t < 4; t++) {
        const int idx = tid + t * 256;
        const int r = idx >> 3, c = (idx & 7) * 8;
        *(uint4*)&sm.Qhi[r][c] = *(const uint4*)(Qhig + r * HD + c);
        *(uint4*)&sm.Qlo[r][c] = *(const uint4*)(Qlog + r * HD + c);
    }
    if (tid < 128) sm.ls[tid] = 0.f;

    float oacc[2][4][4];
    #pragma unroll
    for (int i = 0; i < 2; i++)
        #pragma unroll
        for (int j = 0; j < 4; j++)
            #pragma unroll
            for (int k = 0; k < 4; k++) oacc[i][j][k] = 0.f;

    const float scale = rsqrtf(2048.0f);
    __syncthreads();

    for (int kt = 0; kt <= qt; kt++) {
        const int k0 = kt * 128;
        // Stage K (hi/lo) and Vt (hi/lo) tiles
        #pragma unroll
        for (int t = 0; t < 4; t++) {
            const int idx = tid + t * 256;
            {
                const int r = idx >> 3, c = (idx & 7) * 8;
                *(uint4*)&sm.Khi[r][c] = *(const uint4*)(Khig + (size_t)(k0 + r) * HD + c);
                *(uint4*)&sm.Klo[r][c] = *(const uint4*)(Klog + (size_t)(k0 + r) * HD + c);
            }
            {
                const int r = idx >> 4, c = (idx & 15) * 8;
                *(uint4*)&sm.Vthi[r][c] = *(const uint4*)(Vthig + (size_t)r * LL + k0 + c);
                *(uint4*)&sm.Vtlo[r][c] = *(const uint4*)(Vtlog + (size_t)r * LL + k0 + c);
            }
        }
        __syncthreads();

        // ---- S = Q K^T (3-term bf16 split), warp tile 64x32 ----
        float sacc[4][4][4];
        #pragma unroll
        for (int i = 0; i < 4; i++)
            #pragma unroll
            for (int j = 0; j < 4; j++)
                #pragma unroll
                for (int k = 0; k < 4; k++) sacc[i][j][k] = 0.f;

        #pragma unroll
        for (int ks = 0; ks < 4; ks++) {
            u32 afh[4][4], afl[4][4];
            #pragma unroll
            for (int mt = 0; mt < 4; mt++) {
                const int mr = warp_m * 64 + mt * 16 + (lane & 15);
                const int kc = ks * 16 + (lane >> 4) * 8;
                ldsm4(afh[mt], smem_u32(&sm.Qhi[mr][kc]));
                ldsm4(afl[mt], smem_u32(&sm.Qlo[mr][kc]));
            }
            u32 bfh[2][4], bfl[2][4];
            #pragma unroll
            for (int np = 0; np < 2; np++) {
                const int nr = warp_n * 32 + np * 16 + ((lane >> 4) << 3) + (lane & 7);
                const int kc = ks * 16 + ((lane >> 3) & 1) * 8;
                ldsm4(bfh[np], smem_u32(&sm.Khi[nr][kc]));
                ldsm4(bfl[np], smem_u32(&sm.Klo[nr][kc]));
            }
            #pragma unroll
            for (int mt = 0; mt < 4; mt++) {
                #pragma unroll
                for (int nt = 0; nt < 4; nt++) {
                    const u32* bh_ = &bfh[nt >> 1][(nt & 1) * 2];
                    const u32* bl_ = &bfl[nt >> 1][(nt & 1) * 2];
                    mma16816(sacc[mt][nt], afh[mt], bh_);
                    mma16816(sacc[mt][nt], afh[mt], bl_);
                    mma16816(sacc[mt][nt], afl[mt], bh_);
                }
            }
        }

        // ---- exp + mask -> probs (global) + P (smem bf16 hi/lo) + rowsums ----
        #pragma unroll
        for (int mt = 0; mt < 4; mt++) {
            const int m0 = warp_m * 64 + mt * 16 + (lane >> 2);
            const int qg0 = q0 + m0, qg1 = qg0 + 8;
            float rs0 = 0.f, rs1 = 0.f;
            #pragma unroll
            for (int nt = 0; nt < 4; nt++) {
                const int n = warp_n * 32 + nt * 8 + (lane & 3) * 2;
                const int kg = k0 + n;
                const float* c = sacc[mt][nt];
                float p0 = (kg     <= qg0) ? __expf(c[0] * scale) : 0.f;
                float p1 = (kg + 1 <= qg0) ? __expf(c[1] * scale) : 0.f;
                float p2 = (kg     <= qg1) ? __expf(c[2] * scale) : 0.f;
                float p3 = (kg + 1 <= qg1) ? __expf(c[3] * scale) : 0.f;
                rs0 += p0 + p1; rs1 += p2 + p3;
                *(float2*)(Pb + (size_t)m0 * LL + kg)       = make_float2(p0, p1);
                *(float2*)(Pb + (size_t)(m0 + 8) * LL + kg) = make_float2(p2, p3);
                __nv_bfloat162 h01 = __float22bfloat162_rn(make_float2(p0, p1));
                __nv_bfloat162 h23 = __float22bfloat162_rn(make_float2(p2, p3));
                __nv_bfloat162 l01 = __float22bfloat162_rn(make_float2(
                    p0 - __bfloat162float(h01.x), p1 - __bfloat162float(h01.y)));
                __nv_bfloat162 l23 = __float22bfloat162_rn(make_float2(
                    p2 - __bfloat162float(h23.x), p3 - __bfloat162float(h23.y)));
                *(__nv_bfloat162*)&sm.Phi[m0][n]     = h01;
                *(__nv_bfloat162*)&sm.Phi[m0 + 8][n] = h23;
                *(__nv_bfloat162*)&sm.Plo[m0][n]     = l01;
                *(__nv_bfloat162*)&sm.Plo[m0 + 8][n] = l23;
            }
            rs0 += __shfl_xor_sync(0xffffffffu, rs0, 1);
            rs0 += __shfl_xor_sync(0xffffffffu, rs0, 2);
            rs1 += __shfl_xor_sync(0xffffffffu, rs1, 1);
            rs1 += __shfl_xor_sync(0xffffffffu, rs1, 2);
            if ((lane & 3) == 0) {
                atomicAdd(&sm.ls[m0], rs0);
                atomicAdd(&sm.ls[m0 + 8], rs1);
            }
        }
        __syncthreads();

        // ---- O += P V (3-term split), warp tile 32x32, k = 128 keys ----
        #pragma unroll
        for (int ks = 0; ks < 8; ks++) {
            u32 pfh[2][4], pfl[2][4];
            #pragma unroll
            for (int mt = 0; mt < 2; mt++) {
                const int mr = warp_om * 32 + mt * 16 + (lane & 15);
                const int kc = ks * 16 + (lane >> 4) * 8;
                ldsm4(pfh[mt], smem_u32(&sm.Phi[mr][kc]));
                ldsm4(pfl[mt], smem_u32(&sm.Plo[mr][kc]));
            }
            u32 vfh[2][4], vfl[2][4];
            #pragma unroll
            for (int np = 0; np < 2; np++) {
                const int nr = warp_on * 32 + np * 16 + ((lane >> 4) << 3) + (lane & 7);
                const int kc = ks * 16 + ((lane >> 3) & 1) * 8;
                ldsm4(vfh[np], smem_u32(&sm.Vthi[nr][kc]));
                ldsm4(vfl[np], smem_u32(&sm.Vtlo[nr][kc]));
            }
            #pragma unroll
            for (int mt = 0; mt < 2; mt++) {
                #pragma unroll
                for (int nt = 0; nt < 4; nt++) {
                    const u32* bh_ = &vfh[nt >> 1][(nt & 1) * 2];
                    const u32* bl_ = &vfl[nt >> 1][(nt & 1) * 2];
                    mma16816(oacc[mt][nt], pfh[mt], bh_);
                    mma16816(oacc[mt][nt], pfh[mt], bl_);
                    mma16816(oacc[mt][nt], pfl[mt], bh_);
                }
            }
        }
        __syncthreads();
    }

    // Zero fully-masked probs region (cols >= (qt+1)*128)
    const int zc0 = (qt + 1) * 128;
    if (zc0 < LL) {
        const int w4 = (LL - zc0) >> 2;
        const float4 z = make_float4(0.f, 0.f, 0.f, 0.f);
        for (int idx = tid; idx < 128 * w4; idx += 256) {
            const int r = idx / w4, c = idx - r * w4;
            *(float4*)(Pb + (size_t)r * LL + zc0 + c * 4) = z;
        }
    }

    // Epilogue: O / rowsum -> gAhi/gAlo (bf16 split), plus g_lsum
    #pragma unroll
    for (int mt = 0; mt < 2; mt++) {
        const int m0 = warp_om * 32 + mt * 16 + (lane >> 2);
        const float inv0 = 1.0f / sm.ls[m0];
        const float inv1 = 1.0f / sm.ls[m0 + 8];
        #pragma unroll
        for (int nt = 0; nt < 4; nt++) {
            const int d = warp_on * 32 + nt * 8 + (lane & 3) * 2;
            const float* c = oacc[mt][nt];
            float2 v0 = make_float2(c[0] * inv0, c[1] * inv0);
            float2 v1 = make_float2(c[2] * inv1, c[3] * inv1);
            __nv_bfloat162 h0 = __float22bfloat162_rn(v0);
            __nv_bfloat162 l0 = __float22bfloat162_rn(make_float2(
                v0.x - __bfloat162float(h0.x), v0.y - __bfloat162float(h0.y)));
            __nv_bfloat162 h1 = __float22bfloat162_rn(v1);
            __nv_bfloat162 l1 = __float22bfloat162_rn(make_float2(
                v1.x - __bfloat162float(h1.x), v1.y - __bfloat162float(h1.y)));
            const size_t o0 = ((size_t)(bb * LL + q0 + m0)) * DD + h * HD + d;
            const size_t o1 = ((size_t)(bb * LL + q0 + m0 + 8)) * DD + h * HD + d;
            *(__nv_bfloat162*)(gAhi + o0) = h0;
            *(__nv_bfloat162*)(gAlo + o0) = l0;
            *(__nv_bfloat162*)(gAhi + o1) = h1;
            *(__nv_bfloat162*)(gAlo + o1) = l1;
        }
    }
    if (tid < 128) g_lsum[bh * LL + q0 + tid] = sm.ls[tid];
}

// ---------------------------------------------------------------------------
// Kernel: normalize probs in place by row sums.
// ---------------------------------------------------------------------------
__global__ __launch_bounds__(256) void norm_kernel(float* __restrict__ probs)
{
    const size_t i = ((size_t)blockIdx.x * blockDim.x + threadIdx.x) * 2;
    const size_t row = i >> 9;
    float4 v0 = ((float4*)probs)[i];
    float4 v1 = ((float4*)probs)[i + 1];
    const float inv = 1.0f / g_lsum[row];
    v0.x *= inv; v0.y *= inv; v0.z *= inv; v0.w *= inv;
    v1.x *= inv; v1.y *= inv; v1.z *= inv; v1.w *= inv;
    ((float4*)probs)[i]     = v0;
    ((float4*)probs)[i + 1] = v1;
}

// ---------------------------------------------------------------------------
extern "C" void kernel_launch(void* const* d_in, const int* in_sizes, int n_in,
                              void* d_out, int out_size)
{
    const float* X     = (const float*)d_in[0];
    const float* w_qkv = (const float*)d_in[1];
    const float* b_qkv = (const float*)d_in[2];
    const float* w_out = (const float*)d_in[3];
    const float* b_out = (const float*)d_in[4];

    float* out   = (float*)d_out;
    float* probs = out + (size_t)BB * LL * DD;

    __nv_bfloat16 *xhi, *xlo, *wqh, *wql, *woh, *wol;
    cudaGetSymbolAddress((void**)&xhi, gXhi);
    cudaGetSymbolAddress((void**)&xlo, gXlo);
    cudaGetSymbolAddress((void**)&wqh, gWqkv_hi);
    cudaGetSymbolAddress((void**)&wql, gWqkv_lo);
    cudaGetSymbolAddress((void**)&woh, gWout_hi);
    cudaGetSymbolAddress((void**)&wol, gWout_lo);

    cudaFuncSetAttribute(attn_mma_kernel,
                         cudaFuncAttributeMaxDynamicSharedMemorySize,
                         (int)sizeof(AttnSmem));

    // 0. fp32 -> bf16 hi/lo conversions
    xconv_kernel<<<(BB * LL * DD) / 256, 256>>>(X, xhi, xlo);
    wconv_kernel<<<dim3(ND3 / 32, KDIM / 32), dim3(32, 8)>>>(w_qkv, wqh, wql, KDIM, ND3);
    wconv_kernel<<<dim3(DD / 32, KDIM / 32), dim3(32, 8)>>>(w_out, woh, wol, KDIM, DD);

    // 1. QKV projection (HMMA)
    qkv_mma_kernel<<<dim3(ND3 / 128, (BB * LL) / 128), 256>>>(b_qkv);

    // 2. RoPE (fp32 -> bf16 hi/lo) and V transpose/split
    rope_kernel<<<(BB * HH * LL * 32) / 256, 256>>>();
    vconv_kernel<<<dim3(LL / 32, HD / 32, BB * HH), dim3(32, 8)>>>();

    // 3. Fused attention (HMMA)
    attn_mma_kernel<<<dim3(LL / 128, HH, BB), 256, sizeof(AttnSmem)>>>(probs);

    // 4. Normalize probs
    norm_kernel<<<(int)(((size_t)BB * HH * LL * LL / 8) / 256), 256>>>(probs);

    // 5. Output projection (HMMA)
    out_mma_kernel<<<dim3(DD / 128, (BB * LL) / 128), 256>>>(b_out, out);
}